// round 1
// baseline (speedup 1.0000x reference)
#include <cuda_runtime.h>
#include <cuda_bf16.h>

// Problem constants (fixed by the reference: B=2048, C=16, H=32, W=32 -> F=16384)
#define B_SAMPLES 2048
#define F_FEATS   16384
#define THREADS   256

// Scratch for per-sample results (deterministic two-phase reduction; no
// device allocation allowed, so use a __device__ global).
__device__ float g_per_sample[B_SAMPLES];

__global__ __launch_bounds__(THREADS, 8)
void fnmse_row_kernel(const float* __restrict__ out,
                      const float* __restrict__ tgt,
                      const float* __restrict__ fw)
{
    const int b   = blockIdx.x;
    const int tid = threadIdx.x;

    const float4* __restrict__ o4 = reinterpret_cast<const float4*>(out + (size_t)b * F_FEATS);
    const float4* __restrict__ t4 = reinterpret_cast<const float4*>(tgt + (size_t)b * F_FEATS);
    const float4* __restrict__ w4 = reinterpret_cast<const float4*>(fw);

    float ssq = 0.0f;
    float cnt = 0.0f;

    // F/4 = 4096 float4 per row; 256 threads -> 16 iterations, fully unrolled
    // for deep MLP (front-batched LDG.128s hide DRAM latency).
#pragma unroll
    for (int it = 0; it < (F_FEATS / 4) / THREADS; ++it) {
        const int i = it * THREADS + tid;
        float4 o = o4[i];
        float4 t = t4[i];
        float4 w = w4[i];

        // component x
        {
            bool  m = (t.x == t.x);          // !isnan
            float r = m ? (t.x - o.x) : 0.0f;
            float s = r * w.x;
            ssq = fmaf(s, s, ssq);
            cnt += m ? 1.0f : 0.0f;
        }
        // component y
        {
            bool  m = (t.y == t.y);
            float r = m ? (t.y - o.y) : 0.0f;
            float s = r * w.y;
            ssq = fmaf(s, s, ssq);
            cnt += m ? 1.0f : 0.0f;
        }
        // component z
        {
            bool  m = (t.z == t.z);
            float r = m ? (t.z - o.z) : 0.0f;
            float s = r * w.z;
            ssq = fmaf(s, s, ssq);
            cnt += m ? 1.0f : 0.0f;
        }
        // component w
        {
            bool  m = (t.w == t.w);
            float r = m ? (t.w - o.w) : 0.0f;
            float s = r * w.w;
            ssq = fmaf(s, s, ssq);
            cnt += m ? 1.0f : 0.0f;
        }
    }

    // Warp reduction
#pragma unroll
    for (int off = 16; off > 0; off >>= 1) {
        ssq += __shfl_down_sync(0xFFFFFFFFu, ssq, off);
        cnt += __shfl_down_sync(0xFFFFFFFFu, cnt, off);
    }

    __shared__ float s_ssq[THREADS / 32];
    __shared__ float s_cnt[THREADS / 32];
    const int lane = tid & 31;
    const int wid  = tid >> 5;
    if (lane == 0) { s_ssq[wid] = ssq; s_cnt[wid] = cnt; }
    __syncthreads();

    if (wid == 0) {
        float vs = (lane < THREADS / 32) ? s_ssq[lane] : 0.0f;
        float vc = (lane < THREADS / 32) ? s_cnt[lane] : 0.0f;
#pragma unroll
        for (int off = 4; off > 0; off >>= 1) {
            vs += __shfl_down_sync(0xFFFFFFFFu, vs, off);
            vc += __shfl_down_sync(0xFFFFFFFFu, vc, off);
        }
        if (lane == 0) g_per_sample[b] = vs / vc;
    }
}

__global__ __launch_bounds__(1024, 1)
void fnmse_final_reduce(float* __restrict__ d_out)
{
    const int tid = threadIdx.x;
    float s = 0.0f;
#pragma unroll
    for (int i = tid; i < B_SAMPLES; i += 1024) s += g_per_sample[i];

#pragma unroll
    for (int off = 16; off > 0; off >>= 1)
        s += __shfl_down_sync(0xFFFFFFFFu, s, off);

    __shared__ float smem[32];
    const int lane = tid & 31;
    const int wid  = tid >> 5;
    if (lane == 0) smem[wid] = s;
    __syncthreads();

    if (wid == 0) {
        float v = (lane < 32) ? smem[lane] : 0.0f;
#pragma unroll
        for (int off = 16; off > 0; off >>= 1)
            v += __shfl_down_sync(0xFFFFFFFFu, v, off);
        if (lane == 0) d_out[0] = v;
    }
}

extern "C" void kernel_launch(void* const* d_in, const int* in_sizes, int n_in,
                              void* d_out, int out_size)
{
    // metadata order: output, target, e_exp, sample_weight, feature_weight
    const float* out = (const float*)d_in[0];
    const float* tgt = (const float*)d_in[1];
    // d_in[2] (e_exp) and d_in[3] (sample_weight) are unused by the reference.
    const float* fw  = (const float*)d_in[4];

    fnmse_row_kernel<<<B_SAMPLES, THREADS>>>(out, tgt, fw);
    fnmse_final_reduce<<<1, 1024>>>((float*)d_out);
}

// round 2
// speedup vs baseline: 1.0063x; 1.0063x over previous
#include <cuda_runtime.h>
#include <cuda_bf16.h>

// Problem constants (fixed by the reference: B=2048, C=16, H=32, W=32 -> F=16384)
#define B_SAMPLES 2048
#define F_FEATS   16384
#define THREADS   256

// Scratch: per-sample results + arrival counter (no device allocation allowed).
__device__ float        g_per_sample[B_SAMPLES];
__device__ unsigned int g_arrive_count = 0;   // reset to 0 by the last block each run

__global__ __launch_bounds__(THREADS, 8)
void fnmse_fused_kernel(const float* __restrict__ out,
                        const float* __restrict__ tgt,
                        const float* __restrict__ fw,
                        float* __restrict__ d_out)
{
    const int b   = blockIdx.x;
    const int tid = threadIdx.x;

    const float4* __restrict__ o4 = reinterpret_cast<const float4*>(out + (size_t)b * F_FEATS);
    const float4* __restrict__ t4 = reinterpret_cast<const float4*>(tgt + (size_t)b * F_FEATS);
    const float4* __restrict__ w4 = reinterpret_cast<const float4*>(fw);

    float ssq = 0.0f;
    float cnt = 0.0f;

    // F/4 = 4096 float4 per row; 256 threads -> 16 iterations, fully unrolled
    // for deep MLP (front-batched LDG.128s hide DRAM latency).
#pragma unroll
    for (int it = 0; it < (F_FEATS / 4) / THREADS; ++it) {
        const int i = it * THREADS + tid;
        float4 o = o4[i];
        float4 t = t4[i];
        float4 w = w4[i];

        {
            bool  m = (t.x == t.x);          // !isnan
            float r = m ? (t.x - o.x) : 0.0f;
            float s = r * w.x;
            ssq = fmaf(s, s, ssq);
            cnt += m ? 1.0f : 0.0f;
        }
        {
            bool  m = (t.y == t.y);
            float r = m ? (t.y - o.y) : 0.0f;
            float s = r * w.y;
            ssq = fmaf(s, s, ssq);
            cnt += m ? 1.0f : 0.0f;
        }
        {
            bool  m = (t.z == t.z);
            float r = m ? (t.z - o.z) : 0.0f;
            float s = r * w.z;
            ssq = fmaf(s, s, ssq);
            cnt += m ? 1.0f : 0.0f;
        }
        {
            bool  m = (t.w == t.w);
            float r = m ? (t.w - o.w) : 0.0f;
            float s = r * w.w;
            ssq = fmaf(s, s, ssq);
            cnt += m ? 1.0f : 0.0f;
        }
    }

    // Warp reduction
#pragma unroll
    for (int off = 16; off > 0; off >>= 1) {
        ssq += __shfl_down_sync(0xFFFFFFFFu, ssq, off);
        cnt += __shfl_down_sync(0xFFFFFFFFu, cnt, off);
    }

    __shared__ float s_ssq[THREADS / 32];
    __shared__ float s_cnt[THREADS / 32];
    __shared__ bool  s_is_last;
    const int lane = tid & 31;
    const int wid  = tid >> 5;
    if (lane == 0) { s_ssq[wid] = ssq; s_cnt[wid] = cnt; }
    __syncthreads();

    if (wid == 0) {
        float vs = (lane < THREADS / 32) ? s_ssq[lane] : 0.0f;
        float vc = (lane < THREADS / 32) ? s_cnt[lane] : 0.0f;
#pragma unroll
        for (int off = 4; off > 0; off >>= 1) {
            vs += __shfl_down_sync(0xFFFFFFFFu, vs, off);
            vc += __shfl_down_sync(0xFFFFFFFFu, vc, off);
        }
        if (lane == 0) {
            g_per_sample[b] = vs / vc;
            // Make the per-sample write visible before announcing arrival.
            __threadfence();
            unsigned int prev = atomicAdd(&g_arrive_count, 1u);
            s_is_last = (prev == (unsigned int)(gridDim.x - 1));
        }
    }
    __syncthreads();

    // Last-arriving block performs the final (fixed-order, deterministic) sum.
    if (s_is_last) {
        float s = 0.0f;
#pragma unroll
        for (int i = tid; i < B_SAMPLES; i += THREADS) s += g_per_sample[i];

#pragma unroll
        for (int off = 16; off > 0; off >>= 1)
            s += __shfl_down_sync(0xFFFFFFFFu, s, off);

        if (lane == 0) s_ssq[wid] = s;
        __syncthreads();

        if (wid == 0) {
            float v = (lane < THREADS / 32) ? s_ssq[lane] : 0.0f;
#pragma unroll
            for (int off = 4; off > 0; off >>= 1)
                v += __shfl_down_sync(0xFFFFFFFFu, v, off);
            if (lane == 0) {
                d_out[0] = v;
                // Reset for the next graph replay (exactly one block does this).
                g_arrive_count = 0u;
            }
        }
    }
}

extern "C" void kernel_launch(void* const* d_in, const int* in_sizes, int n_in,
                              void* d_out, int out_size)
{
    // metadata order: output, target, e_exp, sample_weight, feature_weight
    const float* out = (const float*)d_in[0];
    const float* tgt = (const float*)d_in[1];
    // d_in[2] (e_exp) and d_in[3] (sample_weight) are unused by the reference.
    const float* fw  = (const float*)d_in[4];

    fnmse_fused_kernel<<<B_SAMPLES, THREADS>>>(out, tgt, fw, (float*)d_out);
}